// round 2
// baseline (speedup 1.0000x reference)
#include <cuda_runtime.h>
#include <cstdint>

using ull = unsigned long long;

__device__ __forceinline__ ull pack2(float lo, float hi) {
    ull r; asm("mov.b64 %0, {%1, %2};" : "=l"(r) : "f"(lo), "f"(hi)); return r;
}
__device__ __forceinline__ void fma2(ull& d, ull a, ull b) {
    asm("fma.rn.f32x2 %0, %1, %2, %3;" : "=l"(d) : "l"(a), "l"(b), "l"(d));
}
__device__ __forceinline__ ull mul2(ull a, ull b) {
    ull r; asm("mul.rn.f32x2 %0, %1, %2;" : "=l"(r) : "l"(a), "l"(b)); return r;
}

constexpr int NROW = 8192;
constexpr int TOT  = 8192;
constexpr int MULC = 512;

constexpr int BM  = 64;    // n-rows per block
constexpr int BK  = 16;    // u per k-tile
constexpr int BV  = 64;    // v per block
constexpr int TV  = 8;     // v per thread
constexpr int NTH = 256;
constexpr int NK  = MULC / BK;   // 32 k-tiles

// ---------------------------------------------------------------------------
// One segment: out[n, OFF + v*D + i] = scale * sum_u x[n, OFF + u*D + i] * w[u,v]
// ---------------------------------------------------------------------------
template<int D, int OFF>
__global__ void __launch_bounds__(NTH)
seg_kernel(const float* __restrict__ x, const float* __restrict__ w,
           float* __restrict__ out)
{
    constexpr int C   = BK * D;   // floats per row per k-tile (16,48,80,112)
    constexpr int PT  = C / 4;    // floats per load-thread (4 threads per row)
    constexpr int NV4 = PT / 4;   // float4 per load-thread ( = D )

    extern __shared__ float sm[];
    float* xs = sm;                    // [2][C][64]  (col XOR-swizzled)
    float* ws = sm + 2 * C * 64;       // [2][BK][BV]

    const int tid  = threadIdx.x;
    const int lane = tid & 31;
    const int vth  = tid >> 5;         // warp id 0..7 -> v group
    const int r    = tid >> 2;         // x-load row 0..63
    const int q    = tid & 3;          // x-load quarter

    const int vb = blockIdx.x * BV;
    const int nb = blockIdx.y * BM;

    const float* xrow = x + (size_t)(nb + r) * (size_t)TOT + OFF + q * PT;
    const int    wv   = tid & 63;      // v for w-load
    const int    wu0  = tid >> 6;      // base u (0..3), step 4

    float4 xr[NV4];
    float  wrg[4];

    auto load_tile = [&](int k) {
        const float4* p = (const float4*)(xrow + k * C);
        #pragma unroll
        for (int e = 0; e < NV4; ++e) xr[e] = p[e];
        #pragma unroll
        for (int s = 0; s < 4; ++s)
            wrg[s] = w[(size_t)(k * BK + wu0 + s * 4) * MULC + vb + wv];
    };

    auto sts_tile = [&](int buf) {
        float* xb = xs + buf * (C * 64);
        const int col = r ^ (q << 3);
        #pragma unroll
        for (int e = 0; e < NV4; ++e) {
            const int t0 = q * PT + e * 4;
            xb[(t0 + 0) * 64 + col] = xr[e].x;
            xb[(t0 + 1) * 64 + col] = xr[e].y;
            xb[(t0 + 2) * 64 + col] = xr[e].z;
            xb[(t0 + 3) * 64 + col] = xr[e].w;
        }
        float* wb = ws + buf * (BK * BV);
        #pragma unroll
        for (int s = 0; s < 4; ++s)
            wb[(wu0 + s * 4) * BV + wv] = wrg[s];
    };

    ull acc[TV][D] = {};
    const int col2 = 2 * lane;

    auto compute = [&](int buf) {
        const float* xb = xs + buf * (C * 64);
        const float* wb = ws + buf * (BK * BV) + vth * TV;
        #pragma unroll
        for (int u = 0; u < BK; ++u) {
            const float4 wa = *(const float4*)&wb[u * BV];
            const float4 wc = *(const float4*)&wb[u * BV + 4];
            ull w2[TV];
            w2[0] = pack2(wa.x, wa.x); w2[1] = pack2(wa.y, wa.y);
            w2[2] = pack2(wa.z, wa.z); w2[3] = pack2(wa.w, wa.w);
            w2[4] = pack2(wc.x, wc.x); w2[5] = pack2(wc.y, wc.y);
            w2[6] = pack2(wc.z, wc.z); w2[7] = pack2(wc.w, wc.w);
            #pragma unroll
            for (int i = 0; i < D; ++i) {
                const int t  = u * D + i;
                const int qq = t / PT;                 // compile-time folded
                const ull xv = *(const ull*)&xb[t * 64 + (col2 ^ (qq << 3))];
                #pragma unroll
                for (int tv = 0; tv < TV; ++tv) fma2(acc[tv][i], xv, w2[tv]);
            }
        }
    };

    // ---- pipelined main loop -------------------------------------------
    load_tile(0);
    sts_tile(0);
    __syncthreads();

    #pragma unroll 1
    for (int k = 0; k < NK; ++k) {
        const int buf = k & 1;
        if (k + 1 < NK) load_tile(k + 1);
        compute(buf);
        if (k + 1 < NK) sts_tile(buf ^ 1);
        __syncthreads();
    }

    // ---- epilogue: stage in smem (stride 66), then coalesced stores ----
    const float scale = 0.044194173824159216f;   // 1/sqrt(512)
    const ull  s2 = pack2(scale, scale);
    float* so = sm;                              // [BV*D][66], reuse

    #pragma unroll
    for (int tv = 0; tv < TV; ++tv)
        #pragma unroll
        for (int i = 0; i < D; ++i) {
            const int cc = (vth * TV + tv) * D + i;
            const ull v  = mul2(acc[tv][i], s2);
            *(ull*)&so[cc * 66 + col2] = v;      // conflict-free STS.64
        }
    __syncthreads();

    constexpr int W = BV * D;                    // contiguous out span
    const int n = tid >> 2;
    float* orow = out + (size_t)(nb + n) * (size_t)TOT + OFF + vb * D;
    #pragma unroll
    for (int e = 0; e < W / 16; ++e) {
        const int cc = q * 4 + e * 16;
        float4 v;
        v.x = so[(cc + 0) * 66 + n];
        v.y = so[(cc + 1) * 66 + n];
        v.z = so[(cc + 2) * 66 + n];
        v.w = so[(cc + 3) * 66 + n];
        *(float4*)&orow[cc] = v;                 // coalesced STG.128
    }
}

// ---------------------------------------------------------------------------
// launch
// ---------------------------------------------------------------------------
template<int D>
constexpr int smem_bytes() {
    const int mainf = 2 * BK * D * 64 + 2 * BK * BV;  // xs + ws (floats)
    const int epif  = 66 * BV * D;                    // epilogue staging
    return 4 * (mainf > epif ? mainf : epif);
}

extern "C" void kernel_launch(void* const* d_in, const int* in_sizes, int n_in,
                              void* d_out, int out_size)
{
    const float* x  = (const float*)d_in[0];
    const float* w0 = (const float*)d_in[1];
    const float* w1 = (const float*)d_in[2];
    const float* w2 = (const float*)d_in[3];
    const float* w3 = (const float*)d_in[4];
    float* out = (float*)d_out;

    constexpr int S1 = smem_bytes<1>();
    constexpr int S3 = smem_bytes<3>();
    constexpr int S5 = smem_bytes<5>();
    constexpr int S7 = smem_bytes<7>();

    // idempotent; not a stream op, safe under graph capture
    cudaFuncSetAttribute(seg_kernel<1, 0>,    cudaFuncAttributeMaxDynamicSharedMemorySize, S1);
    cudaFuncSetAttribute(seg_kernel<3, 512>,  cudaFuncAttributeMaxDynamicSharedMemorySize, S3);
    cudaFuncSetAttribute(seg_kernel<5, 2048>, cudaFuncAttributeMaxDynamicSharedMemorySize, S5);
    cudaFuncSetAttribute(seg_kernel<7, 4608>, cudaFuncAttributeMaxDynamicSharedMemorySize, S7);

    // grid.x = v-blocks (fast) so blocks sharing the same x-slab run together (L2 reuse)
    dim3 grid(MULC / BV, NROW / BM);

    seg_kernel<1, 0>   <<<grid, NTH, S1>>>(x, w0, out);
    seg_kernel<3, 512> <<<grid, NTH, S3>>>(x, w1, out);
    seg_kernel<5, 2048><<<grid, NTH, S5>>>(x, w2, out);
    seg_kernel<7, 4608><<<grid, NTH, S7>>>(x, w3, out);
}

// round 4
// speedup vs baseline: 2.9178x; 2.9178x over previous
#include <cuda_runtime.h>
#include <cuda_fp16.h>
#include <cstdint>

// ---------------------------------------------------------------------------
// Problem constants
// ---------------------------------------------------------------------------
constexpr int NROW = 8192;
constexpr int TOT  = 8192;
constexpr int ROWS_TOTAL = 131072;   // 8192*(1+3+5+7)

// ---------------------------------------------------------------------------
// Device scratch
// ---------------------------------------------------------------------------
__device__ __align__(128) __half g_xT[(size_t)ROWS_TOTAL * 512];   // fp16 x, K(u)-major
__device__ __align__(128) __half g_wh[4 * 512 * 512];              // w hi, [seg][v][u]
__device__ __align__(128) __half g_wl[4 * 512 * 512];              // w lo

// ---------------------------------------------------------------------------
// PTX helpers (compute_103-safe: cp.async / ldmatrix / mma.sync only)
// ---------------------------------------------------------------------------
__device__ __forceinline__ uint32_t smem_u32(const void* p) {
    uint32_t a;
    asm("{ .reg .u64 t; cvta.to.shared.u64 t, %1; cvt.u32.u64 %0, t; }"
        : "=r"(a) : "l"(p));
    return a;
}
__device__ __forceinline__ uint32_t swz(uint32_t off) {        // SW128 pattern
    return off ^ ((off >> 3) & 0x70);
}
__device__ __forceinline__ void cpa16(uint32_t s, const void* g) {
    asm volatile("cp.async.cg.shared.global [%0], [%1], 16;" :: "r"(s), "l"(g));
}
template<int N> __device__ __forceinline__ void cpwait() {
    asm volatile("cp.async.wait_group %0;" :: "n"(N) : "memory");
}
__device__ __forceinline__ void cpcommit() {
    asm volatile("cp.async.commit_group;" ::: "memory");
}
__device__ __forceinline__ void ldmx4(uint32_t* r, uint32_t addr) {
    asm volatile("ldmatrix.sync.aligned.m8n8.x4.shared.b16 {%0,%1,%2,%3}, [%4];"
        : "=r"(r[0]), "=r"(r[1]), "=r"(r[2]), "=r"(r[3]) : "r"(addr));
}
__device__ __forceinline__ void mma16816(float* c, const uint32_t* a,
                                         uint32_t b0, uint32_t b1) {
    asm volatile(
        "mma.sync.aligned.m16n8k16.row.col.f32.f16.f16.f32 "
        "{%0,%1,%2,%3}, {%4,%5,%6,%7}, {%8,%9}, {%0,%1,%2,%3};"
        : "+f"(c[0]), "+f"(c[1]), "+f"(c[2]), "+f"(c[3])
        : "r"(a[0]), "r"(a[1]), "r"(a[2]), "r"(a[3]), "r"(b0), "r"(b1));
}

// ---------------------------------------------------------------------------
// Prep: w -> wh/wl  (fp16 split, transposed to [v][u] K-major, NO scale)
// ---------------------------------------------------------------------------
__global__ void __launch_bounds__(256)
prep_w(const float* __restrict__ w0, const float* __restrict__ w1,
       const float* __restrict__ w2, const float* __restrict__ w3)
{
    __shared__ float t[32][33];
    const float* w = (blockIdx.z == 0) ? w0 : (blockIdx.z == 1) ? w1
                   : (blockIdx.z == 2) ? w2 : w3;
    const int v0 = blockIdx.x * 32, u0 = blockIdx.y * 32;
    const int tx = threadIdx.x & 31, ty = threadIdx.x >> 5;

    for (int uu = ty; uu < 32; uu += 8)
        t[uu][tx] = w[(size_t)(u0 + uu) * 512 + v0 + tx];
    __syncthreads();

    const size_t segb = (size_t)blockIdx.z * 262144;
    for (int vv = ty; vv < 32; vv += 8) {
        float v = t[tx][vv];                       // w[u0+tx][v0+vv]
        __half h = __float2half_rn(v);
        __half l = __float2half_rn(v - __half2float(h));
        g_wh[segb + (size_t)(v0 + vv) * 512 + u0 + tx] = h;
        g_wl[segb + (size_t)(v0 + vv) * 512 + u0 + tx] = l;
    }
}

// ---------------------------------------------------------------------------
// Prep: x -> xT fp16  ([u][i] -> [(n,i)][u] per segment)
// ---------------------------------------------------------------------------
__global__ void __launch_bounds__(256)
prep_x(const float* __restrict__ x)
{
    __shared__ float sx[3584];
    const int n   = blockIdx.x;
    const int tid = threadIdx.x;

    #pragma unroll
    for (int s = 0; s < 4; ++s) {
        const int d   = (s == 0) ? 1 : (s == 1) ? 3 : (s == 2) ? 5 : 7;
        const int off = (s == 0) ? 0 : (s == 1) ? 512 : (s == 2) ? 2048 : 4608;
        const int rb  = (s == 0) ? 0 : (s == 1) ? 8192 : (s == 2) ? 32768 : 73728;
        const int nf  = 512 * d;

        const float4* src = (const float4*)(x + (size_t)n * TOT + off);
        for (int idx = tid; idx < nf / 4; idx += 256)
            ((float4*)sx)[idx] = src[idx];
        __syncthreads();

        for (int e2 = tid; e2 < nf / 2; e2 += 256) {
            const int e = 2 * e2;
            const int u = e & 511;          // e = i*512 + u
            const int i = e >> 9;
            __half2 p;
            p.x = __float2half_rn(sx[u * d + i]);
            p.y = __float2half_rn(sx[(u + 1) * d + i]);
            *(__half2*)&g_xT[((size_t)rb + (size_t)n * d + i) * 512 + u] = p;
        }
        __syncthreads();
    }
}

// ---------------------------------------------------------------------------
// Main GEMM (mma.sync fp16, 2-pass w-split):
//   C[m=(n,i)][v] = sum_u X[m][u] * (Wh+Wl)[v][u];  out scaled in epilogue.
// CTA tile 128x128, BK=64, double-buffered cp.async.
// ---------------------------------------------------------------------------
constexpr int BUFB     = 49152;            // A 16K + Wh 16K + Wl 16K
constexpr int SMEM_DYN = 2 * BUFB;         // 96 KB

template<int SEG, int D, int OFF, int ROWBASE>
__global__ void __launch_bounds__(256, 1)
gemm_seg(float* __restrict__ out)
{
    extern __shared__ __align__(1024) char sm[];
    const int tid  = threadIdx.x;
    const int lane = tid & 31;
    const int wid  = tid >> 5;
    const int vb   = blockIdx.x * 128;
    const int mb   = blockIdx.y * 128;
    const int wm   = (wid & 1) * 64;       // warp M offset (2x4 warp grid)
    const int wn   = (wid >> 1) * 32;      // warp N offset
    const uint32_t smb = smem_u32(sm);

    const __half* Xt = g_xT + (size_t)ROWBASE * 512;
    const __half* Wh = g_wh + (size_t)SEG * 262144;
    const __half* Wl = g_wl + (size_t)SEG * 262144;

    auto load_chunk = [&](int kc, int buf) {
        const uint32_t base = smb + buf * BUFB;
        const int kcol = kc * 64;
        #pragma unroll
        for (int j = 0; j < 4; ++j) {
            const int idx = tid + j * 256;       // 1024 chunks of 16B per tile
            const int r = idx >> 3, g = idx & 7;
            const uint32_t so_ = swz((uint32_t)(r * 128 + g * 16));
            cpa16(base + so_,         Xt + (size_t)(mb + r) * 512 + kcol + g * 8);
            cpa16(base + 16384 + so_, Wh + (size_t)(vb + r) * 512 + kcol + g * 8);
            cpa16(base + 32768 + so_, Wl + (size_t)(vb + r) * 512 + kcol + g * 8);
        }
        cpcommit();
    };

    float acc[4][4][4] = {};

    // ldmatrix lane addressing
    const int a_m  = (lane & 7) + ((lane >> 3) & 1) * 8;   // + wm + mk*16
    const int a_kb = ((lane >> 4) & 1) * 16;               // + ks*32
    const int b_n  = (lane & 7) + ((lane >> 4) & 1) * 8;   // + wn + nh*16
    const int b_kb = ((lane >> 3) & 1) * 16;

    auto compute = [&](int buf) {
        const uint32_t baseA = smb + buf * BUFB;
        const uint32_t baseH = baseA + 16384;
        const uint32_t baseL = baseA + 32768;
        #pragma unroll
        for (int ks = 0; ks < 4; ++ks) {
            uint32_t a[4][4], bh[2][4], bl[2][4];
            #pragma unroll
            for (int mk = 0; mk < 4; ++mk)
                ldmx4(a[mk], baseA + swz((uint32_t)(
                    (wm + mk * 16 + a_m) * 128 + ks * 32 + a_kb)));
            #pragma unroll
            for (int nh = 0; nh < 2; ++nh) {
                const uint32_t o = swz((uint32_t)(
                    (wn + nh * 16 + b_n) * 128 + ks * 32 + b_kb));
                ldmx4(bh[nh], baseH + o);
                ldmx4(bl[nh], baseL + o);
            }
            #pragma unroll
            for (int mk = 0; mk < 4; ++mk)
                #pragma unroll
                for (int nb = 0; nb < 4; ++nb) {
                    mma16816(acc[mk][nb], a[mk],
                             bh[nb >> 1][(nb & 1) * 2], bh[nb >> 1][(nb & 1) * 2 + 1]);
                    mma16816(acc[mk][nb], a[mk],
                             bl[nb >> 1][(nb & 1) * 2], bl[nb >> 1][(nb & 1) * 2 + 1]);
                }
        }
    };

    load_chunk(0, 0);
    #pragma unroll 1
    for (int k = 0; k < 8; ++k) {
        if (k < 7) { load_chunk(k + 1, (k + 1) & 1); cpwait<1>(); }
        else       { cpwait<0>(); }
        __syncthreads();
        compute(k & 1);
        __syncthreads();
    }

    // ---- epilogue: acc -> smem [m][v] (stride 132) -> contiguous stores ----
    const float SC = 0.044194173824159216f;    // 1/sqrt(512)
    float* so = (float*)sm;
    #pragma unroll
    for (int mk = 0; mk < 4; ++mk)
        #pragma unroll
        for (int nb = 0; nb < 4; ++nb) {
            const int row = wm + mk * 16 + (lane >> 2);
            const int col = wn + nb * 8 + (lane & 3) * 2;
            float2 v0 = make_float2(acc[mk][nb][0] * SC, acc[mk][nb][1] * SC);
            float2 v1 = make_float2(acc[mk][nb][2] * SC, acc[mk][nb][3] * SC);
            *(float2*)&so[row * 132 + col]       = v0;
            *(float2*)&so[(row + 8) * 132 + col] = v1;
        }
    __syncthreads();

    const int n0 = mb / D;
    const int n1 = (mb + 127) / D;
    constexpr int SPAN = 128 * D;              // contiguous out floats per n
    const int total = (n1 - n0 + 1) * SPAN;
    for (int t = tid; t < total; t += 256) {
        const int ni = t / SPAN;
        const int jj = t - ni * SPAN;
        const int n  = n0 + ni;
        const int vl = jj / D;
        const int i  = jj - vl * D;
        const int m  = n * D + i;
        if (m >= mb && m < mb + 128)
            out[(size_t)n * TOT + OFF + (size_t)vb * D + jj] =
                so[(m - mb) * 132 + vl];
    }
}

// ---------------------------------------------------------------------------
// launch
// ---------------------------------------------------------------------------
extern "C" void kernel_launch(void* const* d_in, const int* in_sizes, int n_in,
                              void* d_out, int out_size)
{
    const float* x  = (const float*)d_in[0];
    const float* w0 = (const float*)d_in[1];
    const float* w1 = (const float*)d_in[2];
    const float* w2 = (const float*)d_in[3];
    const float* w3 = (const float*)d_in[4];
    float* out = (float*)d_out;

    cudaFuncSetAttribute(gemm_seg<0, 1, 0,    0>,     cudaFuncAttributeMaxDynamicSharedMemorySize, SMEM_DYN);
    cudaFuncSetAttribute(gemm_seg<1, 3, 512,  8192>,  cudaFuncAttributeMaxDynamicSharedMemorySize, SMEM_DYN);
    cudaFuncSetAttribute(gemm_seg<2, 5, 2048, 32768>, cudaFuncAttributeMaxDynamicSharedMemorySize, SMEM_DYN);
    cudaFuncSetAttribute(gemm_seg<3, 7, 4608, 73728>, cudaFuncAttributeMaxDynamicSharedMemorySize, SMEM_DYN);

    prep_w<<<dim3(16, 16, 4), 256>>>(w0, w1, w2, w3);
    prep_x<<<NROW, 256>>>(x);

    // grid.x = v-tiles (fast) so 4 CTAs sharing an X tile run adjacently (L2 reuse)
    gemm_seg<0, 1, 0,    0>    <<<dim3(4,  64), 256, SMEM_DYN>>>(out);
    gemm_seg<1, 3, 512,  8192> <<<dim3(4, 192), 256, SMEM_DYN>>>(out);
    gemm_seg<2, 5, 2048, 32768><<<dim3(4, 320), 256, SMEM_DYN>>>(out);
    gemm_seg<3, 7, 4608, 73728><<<dim3(4, 448), 256, SMEM_DYN>>>(out);
}

// round 5
// speedup vs baseline: 4.7224x; 1.6185x over previous
#include <cuda_runtime.h>
#include <cuda_fp16.h>
#include <cstdint>

// ---------------------------------------------------------------------------
// Problem constants
// ---------------------------------------------------------------------------
constexpr int NROW = 8192;
constexpr int TOT  = 8192;
constexpr int ROWS_TOTAL = 131072;   // 8192*(1+3+5+7)

// ---------------------------------------------------------------------------
// Device scratch
// ---------------------------------------------------------------------------
__device__ __align__(128) __half g_xT[(size_t)ROWS_TOTAL * 512];   // fp16 x, K(u)-major
__device__ __align__(128) __half g_w[4 * 512 * 512];               // fp16 w, [seg][v][u]

// ---------------------------------------------------------------------------
// PTX helpers (compute_103-safe: cp.async / ldmatrix / mma.sync only)
// ---------------------------------------------------------------------------
__device__ __forceinline__ uint32_t smem_u32(const void* p) {
    uint32_t a;
    asm("{ .reg .u64 t; cvta.to.shared.u64 t, %1; cvt.u32.u64 %0, t; }"
        : "=r"(a) : "l"(p));
    return a;
}
__device__ __forceinline__ uint32_t swz(uint32_t off) {        // SW128 pattern
    return off ^ ((off >> 3) & 0x70);
}
__device__ __forceinline__ void cpa16(uint32_t s, const void* g) {
    asm volatile("cp.async.cg.shared.global [%0], [%1], 16;" :: "r"(s), "l"(g));
}
template<int N> __device__ __forceinline__ void cpwait() {
    asm volatile("cp.async.wait_group %0;" :: "n"(N) : "memory");
}
__device__ __forceinline__ void cpcommit() {
    asm volatile("cp.async.commit_group;" ::: "memory");
}
__device__ __forceinline__ void ldmx4(uint32_t* r, uint32_t addr) {
    asm volatile("ldmatrix.sync.aligned.m8n8.x4.shared.b16 {%0,%1,%2,%3}, [%4];"
        : "=r"(r[0]), "=r"(r[1]), "=r"(r[2]), "=r"(r[3]) : "r"(addr));
}
__device__ __forceinline__ void mma16816(float* c, const uint32_t* a,
                                         uint32_t b0, uint32_t b1) {
    asm volatile(
        "mma.sync.aligned.m16n8k16.row.col.f32.f16.f16.f32 "
        "{%0,%1,%2,%3}, {%4,%5,%6,%7}, {%8,%9}, {%0,%1,%2,%3};"
        : "+f"(c[0]), "+f"(c[1]), "+f"(c[2]), "+f"(c[3])
        : "r"(a[0]), "r"(a[1]), "r"(a[2]), "r"(a[3]), "r"(b0), "r"(b1));
}

// ---------------------------------------------------------------------------
// Prep: w -> fp16, transposed to [v][u] K-major (no scale; scale in epilogue)
// ---------------------------------------------------------------------------
__global__ void __launch_bounds__(256)
prep_w(const float* __restrict__ w0, const float* __restrict__ w1,
       const float* __restrict__ w2, const float* __restrict__ w3)
{
    __shared__ float t[32][33];
    const float* w = (blockIdx.z == 0) ? w0 : (blockIdx.z == 1) ? w1
                   : (blockIdx.z == 2) ? w2 : w3;
    const int v0 = blockIdx.x * 32, u0 = blockIdx.y * 32;
    const int tx = threadIdx.x & 31, ty = threadIdx.x >> 5;

    for (int uu = ty; uu < 32; uu += 8)
        t[uu][tx] = w[(size_t)(u0 + uu) * 512 + v0 + tx];
    __syncthreads();

    const size_t segb = (size_t)blockIdx.z * 262144;
    for (int vv = ty; vv < 32; vv += 8)
        g_w[segb + (size_t)(v0 + vv) * 512 + u0 + tx] = __float2half_rn(t[tx][vv]);
}

// ---------------------------------------------------------------------------
// Prep: x -> xT fp16  ([u][i] -> [(n,i)][u] per segment)
// ---------------------------------------------------------------------------
__global__ void __launch_bounds__(256)
prep_x(const float* __restrict__ x)
{
    __shared__ float sx[3584];
    const int n   = blockIdx.x;
    const int tid = threadIdx.x;

    #pragma unroll
    for (int s = 0; s < 4; ++s) {
        const int d   = (s == 0) ? 1 : (s == 1) ? 3 : (s == 2) ? 5 : 7;
        const int off = (s == 0) ? 0 : (s == 1) ? 512 : (s == 2) ? 2048 : 4608;
        const int rb  = (s == 0) ? 0 : (s == 1) ? 8192 : (s == 2) ? 32768 : 73728;
        const int nf  = 512 * d;

        const float4* src = (const float4*)(x + (size_t)n * TOT + off);
        for (int idx = tid; idx < nf / 4; idx += 256)
            ((float4*)sx)[idx] = src[idx];
        __syncthreads();

        for (int e2 = tid; e2 < nf / 2; e2 += 256) {
            const int e = 2 * e2;
            const int u = e & 511;          // e = i*512 + u
            const int i = e >> 9;
            __half2 p;
            p.x = __float2half_rn(sx[u * d + i]);
            p.y = __float2half_rn(sx[(u + 1) * d + i]);
            *(__half2*)&g_xT[((size_t)rb + (size_t)n * d + i) * 512 + u] = p;
        }
        __syncthreads();
    }
}

// ---------------------------------------------------------------------------
// Main GEMM (mma.sync fp16, single pass):
//   C[m=(n,i)][v] = sum_u X[m][u] * W[v][u];  scaled in fp32 epilogue.
// CTA tile 128x128, BK=64, double-buffered cp.async, 2 CTAs/SM.
// ---------------------------------------------------------------------------
constexpr int BUFB     = 32768;            // X 16K + W 16K
constexpr int SMEM_DYN = 67584;            // max(2*BUFB, epilogue 128*132*4)

template<int SEG, int D, int OFF, int ROWBASE>
__global__ void __launch_bounds__(256, 2)
gemm_seg(float* __restrict__ out)
{
    extern __shared__ __align__(1024) char sm[];
    const int tid  = threadIdx.x;
    const int lane = tid & 31;
    const int wid  = tid >> 5;
    const int vb   = blockIdx.x * 128;
    const int mb   = blockIdx.y * 128;
    const int wm   = (wid & 1) * 64;       // warp M offset (2x4 warp grid)
    const int wn   = (wid >> 1) * 32;      // warp N offset
    const uint32_t smb = smem_u32(sm);

    const __half* Xt = g_xT + (size_t)ROWBASE * 512;
    const __half* W  = g_w  + (size_t)SEG * 262144;

    auto load_chunk = [&](int kc, int buf) {
        const uint32_t base = smb + buf * BUFB;
        const int kcol = kc * 64;
        #pragma unroll
        for (int j = 0; j < 4; ++j) {
            const int idx = tid + j * 256;       // 1024 chunks of 16B per tile
            const int r = idx >> 3, g = idx & 7;
            const uint32_t so_ = swz((uint32_t)(r * 128 + g * 16));
            cpa16(base + so_,         Xt + (size_t)(mb + r) * 512 + kcol + g * 8);
            cpa16(base + 16384 + so_, W  + (size_t)(vb + r) * 512 + kcol + g * 8);
        }
        cpcommit();
    };

    float acc[4][4][4] = {};

    // ldmatrix lane addressing
    const int a_m  = (lane & 7) + ((lane >> 3) & 1) * 8;   // + wm + mk*16
    const int a_kb = ((lane >> 4) & 1) * 16;               // + ks*32
    const int b_n  = (lane & 7) + ((lane >> 4) & 1) * 8;   // + wn + nh*16
    const int b_kb = ((lane >> 3) & 1) * 16;

    auto compute = [&](int buf) {
        const uint32_t baseA = smb + buf * BUFB;
        const uint32_t baseB = baseA + 16384;
        #pragma unroll
        for (int ks = 0; ks < 4; ++ks) {
            uint32_t a[4][4], b[2][4];
            #pragma unroll
            for (int mk = 0; mk < 4; ++mk)
                ldmx4(a[mk], baseA + swz((uint32_t)(
                    (wm + mk * 16 + a_m) * 128 + ks * 32 + a_kb)));
            #pragma unroll
            for (int nh = 0; nh < 2; ++nh)
                ldmx4(b[nh], baseB + swz((uint32_t)(
                    (wn + nh * 16 + b_n) * 128 + ks * 32 + b_kb)));
            #pragma unroll
            for (int mk = 0; mk < 4; ++mk)
                #pragma unroll
                for (int nb = 0; nb < 4; ++nb)
                    mma16816(acc[mk][nb], a[mk],
                             b[nb >> 1][(nb & 1) * 2], b[nb >> 1][(nb & 1) * 2 + 1]);
        }
    };

    load_chunk(0, 0);
    #pragma unroll 1
    for (int k = 0; k < 8; ++k) {
        if (k < 7) { load_chunk(k + 1, (k + 1) & 1); cpwait<1>(); }
        else       { cpwait<0>(); }
        __syncthreads();
        compute(k & 1);
        __syncthreads();
    }

    // ---- epilogue: acc -> smem [m][v] (stride 132) -> contiguous stores ----
    const float SC = 0.044194173824159216f;    // 1/sqrt(512)
    float* so = (float*)sm;
    #pragma unroll
    for (int mk = 0; mk < 4; ++mk)
        #pragma unroll
        for (int nb = 0; nb < 4; ++nb) {
            const int row = wm + mk * 16 + (lane >> 2);
            const int col = wn + nb * 8 + (lane & 3) * 2;
            float2 v0 = make_float2(acc[mk][nb][0] * SC, acc[mk][nb][1] * SC);
            float2 v1 = make_float2(acc[mk][nb][2] * SC, acc[mk][nb][3] * SC);
            *(float2*)&so[row * 132 + col]       = v0;
            *(float2*)&so[(row + 8) * 132 + col] = v1;
        }
    __syncthreads();

    const int n0 = mb / D;
    const int n1 = (mb + 127) / D;
    constexpr int SPAN = 128 * D;              // contiguous out floats per n
    const int total = (n1 - n0 + 1) * SPAN;
    for (int t = tid; t < total; t += 256) {
        const int ni = t / SPAN;
        const int jj = t - ni * SPAN;
        const int n  = n0 + ni;
        const int vl = jj / D;
        const int i  = jj - vl * D;
        const int m  = n * D + i;
        if (m >= mb && m < mb + 128)
            out[(size_t)n * TOT + OFF + (size_t)vb * D + jj] =
                so[(m - mb) * 132 + vl];
    }
}

// ---------------------------------------------------------------------------
// launch
// ---------------------------------------------------------------------------
extern "C" void kernel_launch(void* const* d_in, const int* in_sizes, int n_in,
                              void* d_out, int out_size)
{
    const float* x  = (const float*)d_in[0];
    const float* w0 = (const float*)d_in[1];
    const float* w1 = (const float*)d_in[2];
    const float* w2 = (const float*)d_in[3];
    const float* w3 = (const float*)d_in[4];
    float* out = (float*)d_out;

    cudaFuncSetAttribute(gemm_seg<0, 1, 0,    0>,     cudaFuncAttributeMaxDynamicSharedMemorySize, SMEM_DYN);
    cudaFuncSetAttribute(gemm_seg<1, 3, 512,  8192>,  cudaFuncAttributeMaxDynamicSharedMemorySize, SMEM_DYN);
    cudaFuncSetAttribute(gemm_seg<2, 5, 2048, 32768>, cudaFuncAttributeMaxDynamicSharedMemorySize, SMEM_DYN);
    cudaFuncSetAttribute(gemm_seg<3, 7, 4608, 73728>, cudaFuncAttributeMaxDynamicSharedMemorySize, SMEM_DYN);

    prep_w<<<dim3(16, 16, 4), 256>>>(w0, w1, w2, w3);
    prep_x<<<NROW, 256>>>(x);

    // grid.x = v-tiles (fast) so 4 CTAs sharing an X tile run adjacently (L2 reuse)
    gemm_seg<0, 1, 0,    0>    <<<dim3(4,  64), 256, SMEM_DYN>>>(out);
    gemm_seg<1, 3, 512,  8192> <<<dim3(4, 192), 256, SMEM_DYN>>>(out);
    gemm_seg<2, 5, 2048, 32768><<<dim3(4, 320), 256, SMEM_DYN>>>(out);
    gemm_seg<3, 7, 4608, 73728><<<dim3(4, 448), 256, SMEM_DYN>>>(out);
}

// round 6
// speedup vs baseline: 5.2727x; 1.1165x over previous
#include <cuda_runtime.h>
#include <cuda_fp16.h>
#include <cstdint>

// ---------------------------------------------------------------------------
// Problem constants
// ---------------------------------------------------------------------------
constexpr int NROW = 8192;
constexpr int TOT  = 8192;
constexpr int ROWS_TOTAL = 131072;   // 8192*(1+3+5+7)

// ---------------------------------------------------------------------------
// Device scratch
// ---------------------------------------------------------------------------
__device__ __align__(128) __half g_xT[(size_t)ROWS_TOTAL * 512];   // fp16 x, K(u)-major
__device__ __align__(128) __half g_w[4 * 512 * 512];               // fp16 w, [seg][v][u]

// ---------------------------------------------------------------------------
// PTX helpers (compute_103-safe: cp.async / ldmatrix / mma.sync only)
// ---------------------------------------------------------------------------
__device__ __forceinline__ uint32_t smem_u32(const void* p) {
    uint32_t a;
    asm("{ .reg .u64 t; cvta.to.shared.u64 t, %1; cvt.u32.u64 %0, t; }"
        : "=r"(a) : "l"(p));
    return a;
}
__device__ __forceinline__ uint32_t swz(uint32_t off) {        // SW128 pattern
    return off ^ ((off >> 3) & 0x70);
}
__device__ __forceinline__ void cpa16(uint32_t s, const void* g) {
    asm volatile("cp.async.cg.shared.global [%0], [%1], 16;" :: "r"(s), "l"(g));
}
template<int N> __device__ __forceinline__ void cpwait() {
    asm volatile("cp.async.wait_group %0;" :: "n"(N) : "memory");
}
__device__ __forceinline__ void cpcommit() {
    asm volatile("cp.async.commit_group;" ::: "memory");
}
__device__ __forceinline__ void ldmx4(uint32_t* r, uint32_t addr) {
    asm volatile("ldmatrix.sync.aligned.m8n8.x4.shared.b16 {%0,%1,%2,%3}, [%4];"
        : "=r"(r[0]), "=r"(r[1]), "=r"(r[2]), "=r"(r[3]) : "r"(addr));
}
__device__ __forceinline__ void mma16816(float* c, const uint32_t* a,
                                         uint32_t b0, uint32_t b1) {
    asm volatile(
        "mma.sync.aligned.m16n8k16.row.col.f32.f16.f16.f32 "
        "{%0,%1,%2,%3}, {%4,%5,%6,%7}, {%8,%9}, {%0,%1,%2,%3};"
        : "+f"(c[0]), "+f"(c[1]), "+f"(c[2]), "+f"(c[3])
        : "r"(a[0]), "r"(a[1]), "r"(a[2]), "r"(a[3]), "r"(b0), "r"(b1));
}

// ---------------------------------------------------------------------------
// Prep: w -> fp16, transposed to [v][u] K-major (no scale; scale in epilogue)
// ---------------------------------------------------------------------------
__global__ void __launch_bounds__(256)
prep_w(const float* __restrict__ w0, const float* __restrict__ w1,
       const float* __restrict__ w2, const float* __restrict__ w3)
{
    __shared__ float t[32][33];
    const float* w = (blockIdx.z == 0) ? w0 : (blockIdx.z == 1) ? w1
                   : (blockIdx.z == 2) ? w2 : w3;
    const int v0 = blockIdx.x * 32, u0 = blockIdx.y * 32;
    const int tx = threadIdx.x & 31, ty = threadIdx.x >> 5;

    for (int uu = ty; uu < 32; uu += 8)
        t[uu][tx] = w[(size_t)(u0 + uu) * 512 + v0 + tx];
    __syncthreads();

    const size_t segb = (size_t)blockIdx.z * 262144;
    for (int vv = ty; vv < 32; vv += 8)
        g_w[segb + (size_t)(v0 + vv) * 512 + u0 + tx] = __float2half_rn(t[tx][vv]);
}

// ---------------------------------------------------------------------------
// Prep: x -> xT fp16  ([u][i] -> [(n,i)][u] per segment)
// ---------------------------------------------------------------------------
__global__ void __launch_bounds__(256)
prep_x(const float* __restrict__ x)
{
    __shared__ float sx[3584];
    const int n   = blockIdx.x;
    const int tid = threadIdx.x;

    #pragma unroll
    for (int s = 0; s < 4; ++s) {
        const int d   = (s == 0) ? 1 : (s == 1) ? 3 : (s == 2) ? 5 : 7;
        const int off = (s == 0) ? 0 : (s == 1) ? 512 : (s == 2) ? 2048 : 4608;
        const int rb  = (s == 0) ? 0 : (s == 1) ? 8192 : (s == 2) ? 32768 : 73728;
        const int nf  = 512 * d;

        const float4* src = (const float4*)(x + (size_t)n * TOT + off);
        for (int idx = tid; idx < nf / 4; idx += 256)
            ((float4*)sx)[idx] = src[idx];
        __syncthreads();

        for (int e2 = tid; e2 < nf / 2; e2 += 256) {
            const int e = 2 * e2;
            const int u = e & 511;          // e = i*512 + u
            const int i = e >> 9;
            __half2 p;
            p.x = __float2half_rn(sx[u * d + i]);
            p.y = __float2half_rn(sx[(u + 1) * d + i]);
            *(__half2*)&g_xT[((size_t)rb + (size_t)n * d + i) * 512 + u] = p;
        }
        __syncthreads();
    }
}

// ---------------------------------------------------------------------------
// Main GEMM body (mma.sync fp16, 3-stage pipeline, 1 sync/iter):
//   C[m=(n,i)][v] = sum_u X[m][u] * W[v][u];  scaled in fp32 epilogue.
// CTA tile 128x128, BK=64.
// ---------------------------------------------------------------------------
constexpr int STAGE    = 32768;            // X 16K + W 16K
constexpr int NSTAGE   = 3;
constexpr int SMEM_DYN = NSTAGE * STAGE;   // 96 KB (epilogue needs 67.6 KB)

template<int SEG, int D, int OFF, int ROWBASE>
__device__ __forceinline__ void gemm_body(float* __restrict__ out, int lb, char* sm)
{
    const int tid  = threadIdx.x;
    const int lane = tid & 31;
    const int wid  = tid >> 5;
    const int vb   = (lb & 3) * 128;
    const int mb   = (lb >> 2) * 128;
    const int wm   = (wid & 1) * 64;       // warp M offset (2x4 warp grid)
    const int wn   = (wid >> 1) * 32;      // warp N offset
    const uint32_t smb = smem_u32(sm);

    const __half* Xt = g_xT + (size_t)ROWBASE * 512;
    const __half* W  = g_w  + (size_t)SEG * 262144;

    // gmem load addressing (per thread)
    const int lr = tid >> 3, lg = tid & 7;
    const uint32_t lso = swz((uint32_t)(lr * 128 + lg * 16));

    auto load_chunk = [&](int kc, int buf) {
        const uint32_t base = smb + buf * STAGE;
        const int kcol = kc * 64 + lg * 8;
        #pragma unroll
        for (int j = 0; j < 4; ++j) {
            const int r = lr + j * 32;
            cpa16(base + lso + j * 4096,         Xt + (size_t)(mb + r) * 512 + kcol);
            cpa16(base + 16384 + lso + j * 4096, W  + (size_t)(vb + r) * 512 + kcol);
        }
        cpcommit();
    };

    float acc[4][4][4] = {};

    // ldmatrix lane addressing: hoist everything below the 2 KB granularity.
    // row*128 for mk*16 / nh*16 row-steps = +2048B: above swizzle bits -> additive.
    const int a_m  = (lane & 7) + ((lane >> 3) & 1) * 8;
    const int a_kb = ((lane >> 4) & 1) * 16;
    const int b_n  = (lane & 7) + ((lane >> 4) & 1) * 8;
    const int b_kb = ((lane >> 3) & 1) * 16;
    const uint32_t aBase = (uint32_t)((wm + a_m) * 128 + a_kb);
    const uint32_t bBase = (uint32_t)((wn + b_n) * 128 + b_kb);

    auto compute = [&](int buf) {
        const uint32_t baseA = smb + buf * STAGE;
        const uint32_t baseB = baseA + 16384;
        #pragma unroll
        for (int ks = 0; ks < 4; ++ks) {
            uint32_t a[4][4], b[2][4];
            const uint32_t aA = baseA + swz(aBase + ks * 32);
            const uint32_t bA = baseB + swz(bBase + ks * 32);
            #pragma unroll
            for (int mk = 0; mk < 4; ++mk) ldmx4(a[mk], aA + mk * 2048);
            #pragma unroll
            for (int nh = 0; nh < 2; ++nh) ldmx4(b[nh], bA + nh * 2048);
            #pragma unroll
            for (int mk = 0; mk < 4; ++mk)
                #pragma unroll
                for (int nb = 0; nb < 4; ++nb)
                    mma16816(acc[mk][nb], a[mk],
                             b[nb >> 1][(nb & 1) * 2], b[nb >> 1][(nb & 1) * 2 + 1]);
        }
    };

    load_chunk(0, 0);
    load_chunk(1, 1);
    #pragma unroll 1
    for (int k = 0; k < 8; ++k) {
        if (k < 7) cpwait<1>(); else cpwait<0>();
        __syncthreads();
        compute(k % 3);
        if (k < 6) load_chunk(k + 2, (k + 2) % 3);
    }

    // ---- epilogue: acc -> smem [m][v] (stride 132) -> contiguous stores ----
    __syncthreads();                       // all compute done before smem reuse
    const float SC = 0.044194173824159216f;    // 1/sqrt(512)
    float* so = (float*)sm;
    #pragma unroll
    for (int mk = 0; mk < 4; ++mk)
        #pragma unroll
        for (int nb = 0; nb < 4; ++nb) {
            const int row = wm + mk * 16 + (lane >> 2);
            const int col = wn + nb * 8 + (lane & 3) * 2;
            float2 v0 = make_float2(acc[mk][nb][0] * SC, acc[mk][nb][1] * SC);
            float2 v1 = make_float2(acc[mk][nb][2] * SC, acc[mk][nb][3] * SC);
            *(float2*)&so[row * 132 + col]       = v0;
            *(float2*)&so[(row + 8) * 132 + col] = v1;
        }
    __syncthreads();

    const int n0 = mb / D;
    const int n1 = (mb + 127) / D;
    constexpr int SPAN = 128 * D;              // contiguous out floats per n
    const int total = (n1 - n0 + 1) * SPAN;
    for (int t = tid; t < total; t += 256) {
        const int ni = t / SPAN;
        const int jj = t - ni * SPAN;
        const int n  = n0 + ni;
        const int vl = jj / D;
        const int i  = jj - vl * D;
        const int m  = n * D + i;
        if (m >= mb && m < mb + 128)
            out[(size_t)n * TOT + OFF + (size_t)vb * D + jj] =
                so[(m - mb) * 132 + vl];
    }
}

// Merged kernel: all 4 segments in one launch (single tail wave).
// seg CTA counts: 256 / 768 / 1280 / 1792  (total 4096)
__global__ void __launch_bounds__(256, 2)
gemm_all(float* __restrict__ out)
{
    extern __shared__ __align__(1024) char sm[];
    const int bid = blockIdx.x;
    if      (bid < 256)  gemm_body<0, 1, 0,    0>    (out, bid,        sm);
    else if (bid < 1024) gemm_body<1, 3, 512,  8192> (out, bid - 256,  sm);
    else if (bid < 2304) gemm_body<2, 5, 2048, 32768>(out, bid - 1024, sm);
    else                 gemm_body<3, 7, 4608, 73728>(out, bid - 2304, sm);
}

// ---------------------------------------------------------------------------
// launch
// ---------------------------------------------------------------------------
extern "C" void kernel_launch(void* const* d_in, const int* in_sizes, int n_in,
                              void* d_out, int out_size)
{
    const float* x  = (const float*)d_in[0];
    const float* w0 = (const float*)d_in[1];
    const float* w1 = (const float*)d_in[2];
    const float* w2 = (const float*)d_in[3];
    const float* w3 = (const float*)d_in[4];
    float* out = (float*)d_out;

    cudaFuncSetAttribute(gemm_all, cudaFuncAttributeMaxDynamicSharedMemorySize, SMEM_DYN);

    prep_w<<<dim3(16, 16, 4), 256>>>(w0, w1, w2, w3);
    prep_x<<<NROW, 256>>>(x);

    gemm_all<<<4096, 256, SMEM_DYN>>>(out);
}